// round 12
// baseline (speedup 1.0000x reference)
#include <cuda_runtime.h>
#include <cuda_fp16.h>
#include <math.h>
#include <stdint.h>

#define BATCH 4
#define SEQ_N 1024
#define SEQ_K 1024
#define DIMF  2048
#define NHEAD 16
#define DHEAD 64
#define ROUTES 2
#define HPR   (NHEAD/ROUTES)
#define DHID  (NHEAD*DHEAD)   // 1024

// ---------------- scratch (static device allocations) ----------------
__device__ __half h_xn[(size_t)BATCH*SEQ_N*DIMF];
__device__ __half h_cn[(size_t)BATCH*ROUTES*SEQ_K*DIMF];
__device__ __half h_q [(size_t)BATCH*NHEAD*SEQ_N*DHEAD];
__device__ __half h_k [(size_t)BATCH*NHEAD*SEQ_K*DHEAD];
__device__ __half h_v [(size_t)BATCH*NHEAD*SEQ_K*DHEAD];
__device__ __half h_ao[(size_t)BATCH*SEQ_N*DHID];
__device__ __half h_wq [(size_t)DHID*DIMF];
__device__ __half h_wkv[(size_t)2*DHID*DIMF];
__device__ __half h_wo [(size_t)DIMF*DHID];

// ---------------- helpers ----------------
__device__ __forceinline__ void cp16(void* dst_smem, const void* src) {
    uint32_t d = (uint32_t)__cvta_generic_to_shared(dst_smem);
    asm volatile("cp.async.cg.shared.global [%0], [%1], 16;" :: "r"(d), "l"(src));
}
__device__ __forceinline__ void mma16h(float* c, const uint32_t* a, uint32_t b0, uint32_t b1) {
    asm volatile("mma.sync.aligned.m16n8k16.row.col.f32.f16.f16.f32 "
        "{%0,%1,%2,%3},{%4,%5,%6,%7},{%8,%9},{%0,%1,%2,%3};"
        : "+f"(c[0]), "+f"(c[1]), "+f"(c[2]), "+f"(c[3])
        : "r"(a[0]), "r"(a[1]), "r"(a[2]), "r"(a[3]), "r"(b0), "r"(b1));
}
// fp16-accumulate variant: C/D are 2x .f16x2 registers
__device__ __forceinline__ void mma16hh(uint32_t* c, const uint32_t* a, uint32_t b0, uint32_t b1) {
    asm volatile("mma.sync.aligned.m16n8k16.row.col.f16.f16.f16.f16 "
        "{%0,%1},{%2,%3,%4,%5},{%6,%7},{%0,%1};"
        : "+r"(c[0]), "+r"(c[1])
        : "r"(a[0]), "r"(a[1]), "r"(a[2]), "r"(a[3]), "r"(b0), "r"(b1));
}
__device__ __forceinline__ void ldsm4(uint32_t* r, uint32_t addr) {
    asm volatile("ldmatrix.sync.aligned.m8n8.x4.shared.b16 {%0,%1,%2,%3}, [%4];"
        : "=r"(r[0]), "=r"(r[1]), "=r"(r[2]), "=r"(r[3]) : "r"(addr));
}
__device__ __forceinline__ void ldsm4t(uint32_t* r, uint32_t addr) {
    asm volatile("ldmatrix.sync.aligned.m8n8.x4.trans.shared.b16 {%0,%1,%2,%3}, [%4];"
        : "=r"(r[0]), "=r"(r[1]), "=r"(r[2]), "=r"(r[3]) : "r"(addr));
}
__device__ __forceinline__ uint32_t s2u(const void* p) {
    uint32_t a;
    asm("{ .reg .u64 t; cvta.to.shared.u64 t, %1; cvt.u32.u64 %0, t; }"
        : "=r"(a) : "l"(p));
    return a;
}
__device__ __forceinline__ uint32_t packh2(float a, float b) {
    __half2 h = __floats2half2_rn(a, b);
    return *(uint32_t*)&h;
}

// ---------------- merged prep: rmsnorm rows + weight conversion ----------------
#define WQ_N4  ((DHID * DIMF) / 4)
#define WKV_N4 ((2 * DHID * DIMF) / 4)
#define WO_N4  ((DIMF * DHID) / 4)
#define W_TOTAL_N4 (WQ_N4 + WKV_N4 + WO_N4)
#define NORM_ROWS (BATCH * SEQ_N + BATCH * ROUTES * SEQ_K)   // 12288
#define WBLOCKS   ((W_TOTAL_N4 + 255) / 256)                 // 8192

__global__ void __launch_bounds__(256) prep_kernel(
    const float* __restrict__ x, const float* __restrict__ ctx,
    const float* __restrict__ gamma,
    const float4* __restrict__ Wq, const float4* __restrict__ Wkv,
    const float4* __restrict__ Wo)
{
    const int blk = blockIdx.x;
    const int t = threadIdx.x;

    if (blk >= NORM_ROWS) {
        int i = (blk - NORM_ROWS) * 256 + t;
        if (i >= W_TOTAL_N4) return;
        const float4* src;
        __half2* dst;
        int j = i;
        if (j < WQ_N4)                  { src = Wq;  dst = (__half2*)h_wq; }
        else if ((j -= WQ_N4) < WKV_N4) { src = Wkv; dst = (__half2*)h_wkv; }
        else { j -= WKV_N4;               src = Wo;  dst = (__half2*)h_wo; }
        float4 v = src[j];
        dst[2 * j]     = __floats2half2_rn(v.x, v.y);
        dst[2 * j + 1] = __floats2half2_rn(v.z, v.w);
        return;
    }

    const long row = blk;
    const float* in;
    __half* out;
    if (row < BATCH * SEQ_N) {
        in  = x + row * (long)DIMF;
        out = h_xn + row * (long)DIMF;
    } else {
        long r = row - BATCH * SEQ_N;
        in  = ctx + r * (long)DIMF;
        out = h_cn + r * (long)DIMF;
    }
    const float4* xr = (const float4*)in;
    const float4* g4 = (const float4*)gamma;

    float4 v0 = xr[2 * t];
    float4 v1 = xr[2 * t + 1];
    float ss = v0.x*v0.x + v0.y*v0.y + v0.z*v0.z + v0.w*v0.w
             + v1.x*v1.x + v1.y*v1.y + v1.z*v1.z + v1.w*v1.w;
    #pragma unroll
    for (int o = 16; o; o >>= 1) ss += __shfl_xor_sync(0xffffffffu, ss, o);
    __shared__ float red[8];
    if ((t & 31) == 0) red[t >> 5] = ss;
    __syncthreads();
    float tot = 0.f;
    #pragma unroll
    for (int i = 0; i < 8; i++) tot += red[i];
    const float s = sqrtf((float)DIMF) / fmaxf(sqrtf(tot), 1e-12f);

    float4 ga = g4[2 * t], gb = g4[2 * t + 1];
    uint4 pk;
    pk.x = packh2(v0.x*s*ga.x, v0.y*s*ga.y);
    pk.y = packh2(v0.z*s*ga.z, v0.w*s*ga.w);
    pk.z = packh2(v1.x*s*gb.x, v1.y*s*gb.y);
    pk.w = packh2(v1.z*s*gb.z, v1.w*s*gb.w);
    ((uint4*)out)[t] = pk;
}

// ---------------- fp16 tensor-core GEMM core ----------------
// CTA tile 128x128, BK=64 halves (128B rows), 3-stage cp.async (96KB smem),
// 256 threads (8 warps 2x4), warp tile 64x32.
#define GH_STAGE 32768
#define GH_SMEM  (3 * GH_STAGE)

// ---- merged Q + KV projection (K = 2048), fp32 accum, 2 CTAs/SM ----
__global__ void __launch_bounds__(256, 2) gemm_qkv(
    const float* __restrict__ sq, const float* __restrict__ skv)
{
    constexpr int K  = DIMF;
    constexpr int NC = K / 64;

    extern __shared__ char smem[];
    const uint32_t smu = s2u(smem);

    const int id = blockIdx.x;
    const bool isQ = (id < 256);
    int bm, bn, bz = 0;
    const __half *A, *Bp;
    if (isQ) {
        bm = id >> 3; bn = id & 7;
        A  = h_xn + (size_t)bm * 128 * K;
        Bp = h_wq + (size_t)bn * 128 * K;
    } else {
        int r = id - 256;
        bz = r >> 6;
        int rr = r & 63;
        bm = rr >> 3; bn = rr & 7;
        A  = h_cn + ((size_t)bz * SEQ_K + (size_t)bm * 128) * K;
        Bp = h_wkv + (size_t)(bz & 1) * DHID * K + (size_t)bn * 128 * K;
    }

    const int tid = threadIdx.x;
    const int lane = tid & 31, warp = tid >> 5;
    const int wm = warp >> 2, wn = warp & 3;
    const int g = lane >> 2, cq = lane & 3;

    const int lr = tid >> 3, lg = tid & 7;
    const int lsw = (lg ^ (lr & 7)) << 4;
    auto load_chunk = [&](int c, int st) {
        char* aB = smem + st * GH_STAGE;
        char* bB = aB + 16384;
        const size_t ko = (size_t)c * 64 + lg * 8;
        #pragma unroll
        for (int t4 = 0; t4 < 4; t4++)
            cp16(aB + (lr + t4 * 32) * 128 + lsw, A + (size_t)(lr + t4 * 32) * K + ko);
        #pragma unroll
        for (int t4 = 0; t4 < 4; t4++)
            cp16(bB + (lr + t4 * 32) * 128 + lsw, Bp + (size_t)(lr + t4 * 32) * K + ko);
    };

    const int lrow = lane & 15, hi = lane >> 4;
    const int sw = lane & 7;
    int moff[4], noff[2];
    #pragma unroll
    for (int mt = 0; mt < 4; mt++) moff[mt] = (wm * 64 + mt * 16 + lrow) * 128;
    #pragma unroll
    for (int p = 0; p < 2; p++)    noff[p]  = (wn * 32 + p * 16 + lrow) * 128 + 16384;

    float c[4][4][4];
    #pragma unroll
    for (int mt = 0; mt < 4; mt++)
        #pragma unroll
        for (int nt = 0; nt < 4; nt++)
            #pragma unroll
            for (int i = 0; i < 4; i++) c[mt][nt][i] = 0.f;

    load_chunk(0, 0);
    asm volatile("cp.async.commit_group;");
    load_chunk(1, 1);
    asm volatile("cp.async.commit_group;");

    #pragma unroll 1
    for (int t = 0; t < NC; t++) {
        asm volatile("cp.async.wait_group 1;");
        __syncthreads();

        if (t + 2 < NC) load_chunk(t + 2, (t + 2) % 3);
        asm volatile("cp.async.commit_group;");

        const uint32_t sb = smu + (t % 3) * GH_STAGE;

        #pragma unroll
        for (int ks = 0; ks < 4; ks++) {
            const int koff = ((2 * ks + hi) ^ sw) << 4;
            uint32_t af[4][4], bf[2][4];
            #pragma unroll
            for (int mt = 0; mt < 4; mt++) ldsm4(af[mt], sb + moff[mt] + koff);
            #pragma unroll
            for (int p = 0; p < 2; p++)    ldsm4(bf[p], sb + noff[p] + koff);
            #pragma unroll
            for (int mt = 0; mt < 4; mt++)
                #pragma unroll
                for (int nt = 0; nt < 4; nt++)
                    mma16h(c[mt][nt], af[mt], bf[nt >> 1][nt & 1], bf[nt >> 1][(nt & 1) + 2]);
        }
    }

    // ---- epilogue ----
    #pragma unroll
    for (int mt = 0; mt < 4; mt++) {
        #pragma unroll
        for (int i = 0; i < 2; i++) {
            const int m = bm * 128 + wm * 64 + mt * 16 + g + i * 8;
            const float srow = isQ ? sq[m] * 0.125f : skv[(size_t)bz * SEQ_K + m];
            #pragma unroll
            for (int nt = 0; nt < 4; nt++) {
                const int o = bn * 128 + wn * 32 + (nt >> 1) * 16 + (nt & 1) * 8 + 2 * cq;
                float v0 = c[mt][nt][i * 2 + 0];
                float v1 = c[mt][nt][i * 2 + 1];
                __half2 hv = __floats2half2_rn(v0 * srow, v1 * srow);
                if (isQ) {
                    int b = m >> 10, nn = m & 1023;
                    int h = o >> 6,  d  = o & 63;
                    *(__half2*)&h_q[(((size_t)(b * NHEAD + h)) * SEQ_N + nn) * DHEAD + d] = hv;
                } else {
                    int hp = o >> 7, dd = o & 127;
                    int b = bz >> 1, rt = bz & 1;
                    size_t base = (((size_t)(b * NHEAD + rt * HPR + hp)) * SEQ_K + m) * DHEAD;
                    if (dd < DHEAD) *(__half2*)&h_k[base + dd]         = hv;
                    else            *(__half2*)&h_v[base + dd - DHEAD] = hv;
                }
            }
        }
    }
}

// ---- O projection (K = 1024): EXPERIMENT — fp16-accumulate mma, per-chunk
// fp32 promotion. 1 CTA/SM (registers), same 128x128 tile / 64x32 warp tile.
__global__ void __launch_bounds__(256) gemm_o(float* __restrict__ out)
{
    constexpr int K  = DHID;
    constexpr int NC = K / 64;

    extern __shared__ char smem[];
    const uint32_t smu = s2u(smem);

    const int bm = blockIdx.y, bn = blockIdx.x;
    const int tid = threadIdx.x;
    const int lane = tid & 31, warp = tid >> 5;
    const int wm = warp >> 2, wn = warp & 3;
    const int g = lane >> 2, cq = lane & 3;

    const __half* A  = h_ao + (size_t)bm * 128 * K;
    const __half* Bp = h_wo + (size_t)bn * 128 * K;

    const int lr = tid >> 3, lg = tid & 7;
    const int lsw = (lg ^ (lr & 7)) << 4;
    auto load_chunk = [&](int c, int st) {
        char* aB = smem + st * GH_STAGE;
        char* bB = aB + 16384;
        const size_t ko = (size_t)c * 64 + lg * 8;
        #pragma unroll
        for (int t4 = 0; t4 < 4; t4++)
            cp16(aB + (lr + t4 * 32) * 128 + lsw, A + (size_t)(lr + t4 * 32) * K + ko);
        #pragma unroll
        for (int t4 = 0; t4 < 4; t4++)
            cp16(bB + (lr + t4 * 32) * 128 + lsw, Bp + (size_t)(lr + t4 * 32) * K + ko);
    };

    const int lrow = lane & 15, hi = lane >> 4;
    const int sw = lane & 7;
    int moff[4], noff[2];
    #pragma unroll
    for (int mt = 0; mt < 4; mt++) moff[mt] = (wm * 64 + mt * 16 + lrow) * 128;
    #pragma unroll
    for (int p = 0; p < 2; p++)    noff[p]  = (wn * 32 + p * 16 + lrow) * 128 + 16384;

    float c[4][4][4];
    #pragma unroll
    for (int mt = 0; mt < 4; mt++)
        #pragma unroll
        for (int nt = 0; nt < 4; nt++)
            #pragma unroll
            for (int i = 0; i < 4; i++) c[mt][nt][i] = 0.f;

    load_chunk(0, 0);
    asm volatile("cp.async.commit_group;");
    load_chunk(1, 1);
    asm volatile("cp.async.commit_group;");

    #pragma unroll 1
    for (int t = 0; t < NC; t++) {
        asm volatile("cp.async.wait_group 1;");
        __syncthreads();

        if (t + 2 < NC) load_chunk(t + 2, (t + 2) % 3);
        asm volatile("cp.async.commit_group;");

        const uint32_t sb = smu + (t % 3) * GH_STAGE;

        // fp16 accumulators for this chunk
        uint32_t hc[4][4][2];
        #pragma unroll
        for (int mt = 0; mt < 4; mt++)
            #pragma unroll
            for (int nt = 0; nt < 4; nt++) { hc[mt][nt][0] = 0u; hc[mt][nt][1] = 0u; }

        #pragma unroll
        for (int ks = 0; ks < 4; ks++) {
            const int koff = ((2 * ks + hi) ^ sw) << 4;
            uint32_t af[4][4], bf[2][4];
            #pragma unroll
            for (int mt = 0; mt < 4; mt++) ldsm4(af[mt], sb + moff[mt] + koff);
            #pragma unroll
            for (int p = 0; p < 2; p++)    ldsm4(bf[p], sb + noff[p] + koff);
            #pragma unroll
            for (int mt = 0; mt < 4; mt++)
                #pragma unroll
                for (int nt = 0; nt < 4; nt++)
                    mma16hh(hc[mt][nt], af[mt], bf[nt >> 1][nt & 1], bf[nt >> 1][(nt & 1) + 2]);
        }

        // promote chunk partials to fp32
        #pragma unroll
        for (int mt = 0; mt < 4; mt++)
            #pragma unroll
            for (int nt = 0; nt < 4; nt++) {
                float2 lo = __half22float2(*(__half2*)&hc[mt][nt][0]);
                float2 hi2 = __half22float2(*(__half2*)&hc[mt][nt][1]);
                c[mt][nt][0] += lo.x;  c[mt][nt][1] += lo.y;
                c[mt][nt][2] += hi2.x; c[mt][nt][3] += hi2.y;
            }
    }

    #pragma unroll
    for (int mt = 0; mt < 4; mt++) {
        #pragma unroll
        for (int i = 0; i < 2; i++) {
            const int m = bm * 128 + wm * 64 + mt * 16 + g + i * 8;
            #pragma unroll
            for (int nt = 0; nt < 4; nt++) {
                const int o = bn * 128 + wn * 32 + (nt >> 1) * 16 + (nt & 1) * 8 + 2 * cq;
                *(float2*)&out[(size_t)m * DIMF + o] =
                    make_float2(c[mt][nt][i * 2 + 0], c[mt][nt][i * 2 + 1]);
            }
        }
    }
}

// ---------------- fp16 flash attention, P kept in registers ----------------
#define AT_SMEM 49664

__global__ void __launch_bounds__(256, 2) attn_fp16(const float* __restrict__ nullkv)
{
    extern __shared__ __half sh[];
    __half* qs = sh;
    __half* ks = sh + 8192;
    __half* vs = sh + 16384;
    float* nk = (float*)(sh + 24576);
    float* nv = nk + 64;
    const uint32_t smu = s2u(sh);

    const int bh = blockIdx.y, h = bh & (NHEAD - 1);
    const int qbase = blockIdx.x * 128;
    const int tid = threadIdx.x, lane = tid & 31, w = tid >> 5;
    const int g = lane >> 2, cq = lane & 3;
    const int lrow = lane & 15, hi = lane >> 4;
    const int sw = lane & 7;

    const __half* qg = h_q + ((size_t)bh * SEQ_N + qbase) * DHEAD;
    const __half* kgp = h_k + (size_t)bh * SEQ_K * DHEAD;
    const __half* vgp = h_v + (size_t)bh * SEQ_K * DHEAD;

    #pragma unroll
    for (int i = 0; i < 4; i++) {
        int idx = tid + i * 256;
        int r = idx >> 3, gg = idx & 7;
        cp16(qs + r * 64 + ((gg ^ (r & 7)) << 3), qg + (size_t)r * DHEAD + gg * 8);
    }
    if (tid < 64)       nk[tid]      = nullkv[h * DHEAD + tid];
    else if (tid < 128) nv[tid - 64] = nullkv[NHEAD * DHEAD + h * DHEAD + (tid - 64)];

    auto load_kv = [&](int tile, int buf) {
        const __half* kt = kgp + (size_t)tile * 64 * DHEAD;
        const __half* vt = vgp + (size_t)tile * 64 * DHEAD;
        __half* kd = ks + buf * 4096;
        __half* vd = vs + buf * 4096;
        #pragma unroll
        for (int i = 0; i < 2; i++) {
            int idx = tid + i * 256;
            int r = idx >> 3, gg = idx & 7;
            int off = r * 64 + ((gg ^ (r & 7)) << 3);
            cp16(kd + off, kt + (size_t)r * DHEAD + gg * 8);
            cp16(vd + off, vt + (size_t)r * DHEAD + gg * 8);
        }
    };
    load_kv(0, 0);
    asm volatile("cp.async.commit_group;");

    asm volatile("cp.async.wait_group 0;");
    __syncthreads();

    float m0, m1, l0 = 1.f, l1 = 1.f;
    {
        int row = w * 16 + lrow;
        int halfo = hi * 32;
        float s = 0.f;
        #pragma unroll
        for (int d = 0; d < 32; d++) {
            int cidx = halfo + d;
            int gg = cidx >> 3;
            float qv = __half2float(qs[row * 64 + ((gg ^ (row & 7)) << 3) + (cidx & 7)]);
            s += qv * nk[cidx];
        }
        s += __shfl_xor_sync(0xffffffffu, s, 16);
        m0 = __shfl_sync(0xffffffffu, s, g);
        m1 = __shfl_sync(0xffffffffu, s, g + 8);
    }
    float o[8][4];
    #pragma unroll
    for (int nt = 0; nt < 8; nt++) {
        float va = nv[nt * 8 + 2 * cq], vb = nv[nt * 8 + 2 * cq + 1];
        o[nt][0] = va; o[nt][1] = vb; o[nt][2] = va; o[nt][3] = vb;
    }

    const uint32_t aqbase = smu + (w * 16 + lrow) * 128;

    #pragma unroll 1
    for (int t = 0; t < 16; t++) {
        if (t > 0) {
            asm volatile("cp.async.wait_group 0;");
            __syncthreads();
        }
        if (t + 1 < 16) load_kv(t + 1, (t + 1) & 1);
        asm volatile("cp.async.commit_group;");

        const uint32_t kbB = smu + 16384 + (t & 1) * 8192 + lrow * 128;
        const uint32_t vbB = smu + 32768 + (t & 1) * 8192 + lrow * 128;

        float s[8][4];
        #pragma unroll
        for (int nt = 0; nt < 8; nt++)
            s[nt][0] = s[nt][1] = s[nt][2] = s[nt][3] = 0.f;

        #pragma unroll
        for (int kst = 0; kst < 4; kst++) {
            const int koff = ((2 * kst + hi) ^ sw) << 4;
            uint32_t af[4], bf[4][4];
            ldsm4(af, aqbase + koff);
            #pragma unroll
            for (int p = 0; p < 4; p++) ldsm4(bf[p], kbB + p * 2048 + koff);
            #pragma unroll
            for (int nt = 0; nt < 8; nt++)
                mma16h(s[nt], af, bf[nt >> 1][nt & 1], bf[nt >> 1][(nt & 1) + 2]);
        }

        float mx0 = -1e30f, mx1 = -1e30f;
        #pragma unroll
        for (int nt = 0; nt < 8; nt++) {
            mx0 = fmaxf(mx0, fmaxf(s[nt][0], s[nt][1]));
            mx1 = fmaxf(mx1, fmaxf(s[nt][2], s[nt][3]));
        }
        mx0 = fmaxf(mx0, __shfl_xor_sync(0xffffffffu, mx0, 1));
        mx0 = fmaxf(mx0, __shfl_xor_sync(0xffffffffu, mx0, 2));
        mx1 = fmaxf(mx1, __shfl_xor_sync(0xffffffffu, mx1, 1));
        mx1 = fmaxf(mx1, __shfl_xor_sync(0xffffffffu, mx1, 2));
        float mn0 = fmaxf(m0, mx0), mn1 = fmaxf(m1, mx1);
        float c0 = __expf(m0 - mn0), c1 = __expf(m1 - mn1);
        float p0 = 0.f, p1 = 0.f;
        #pragma unroll
        for (int nt = 0; nt < 8; nt++) {
            s[nt][0] = __expf(s[nt][0] - mn0);
            s[nt][1] = __expf(s[nt][1] - mn0);
            s[nt][2] = __expf(s[nt][2] - mn1);
            s[nt][3] = __expf(s[nt][3] - mn1);
            p0 += s[nt][0] + s[nt][1];
            p1 += s[nt][2] + s[nt][3];
        }
        p0 += __shfl_xor_sync(0xffffffffu, p0, 1);
        p0 += __shfl_xor_sync(0xffffffffu, p0, 2);
        p1 += __shfl_xor_sync(0xffffffffu, p1, 1);
        p1 += __shfl_xor_sync(0xffffffffu, p1, 2);
        l0 = l0 * c0 + p0; l1 = l1 * c1 + p1;
        m0 = mn0; m1 = mn1;
        #pragma unroll
        for (int nt = 0; nt < 8; nt++) {
            o[nt][0] *= c0; o[nt][1] *= c0;
            o[nt][2] *= c1; o[nt][3] *= c1;
        }

        #pragma unroll
        for (int kc = 0; kc < 4; kc++) {
            uint32_t ap[4];
            ap[0] = packh2(s[2 * kc][0],     s[2 * kc][1]);
            ap[1] = packh2(s[2 * kc][2],     s[2 * kc][3]);
            ap[2] = packh2(s[2 * kc + 1][0], s[2 * kc + 1][1]);
            ap[3] = packh2(s[2 * kc + 1][2], s[2 * kc + 1][3]);
            #pragma unroll
            for (int nt2 = 0; nt2 < 4; nt2++) {
                const int voff = ((nt2 * 2 + hi) ^ sw) << 4;
                uint32_t tv[4];
                ldsm4t(tv, vbB + kc * 2048 + voff);
                mma16h(o[2 * nt2],     ap, tv[0], tv[1]);
                mma16h(o[2 * nt2 + 1], ap, tv[2], tv[3]);
            }
        }
    }

    const int b = bh >> 4;
    const float i0 = 1.f / l0, i1 = 1.f / l1;
    const int n0 = qbase + w * 16 + g;
    const size_t base0 = ((size_t)(b * SEQ_N + n0)) * DHID + h * DHEAD;
    const size_t base1 = ((size_t)(b * SEQ_N + n0 + 8)) * DHID + h * DHEAD;
    #pragma unroll
    for (int nt = 0; nt < 8; nt++) {
        int col = nt * 8 + 2 * cq;
        *(__half2*)&h_ao[base0 + col] = __floats2half2_rn(o[nt][0] * i0, o[nt][1] * i0);
        *(__half2*)&h_ao[base1 + col] = __floats2half2_rn(o[nt][2] * i1, o[nt][3] * i1);
    }
}

// ---------------- launch ----------------
extern "C" void kernel_launch(void* const* d_in, const int* in_sizes, int n_in,
                              void* d_out, int out_size)
{
    const float* x      = (const float*)d_in[0];
    const float* ctx    = (const float*)d_in[1];
    const float* skv    = (const float*)d_in[2];
    const float* sq     = (const float*)d_in[3];
    const float* gamma  = (const float*)d_in[4];
    const float* nullkv = (const float*)d_in[5];
    const float* Wq     = (const float*)d_in[6];
    const float* Wkv    = (const float*)d_in[7];
    const float* Wo     = (const float*)d_in[8];
    float* out = (float*)d_out;

    static int smem_set = 0;
    if (!smem_set) {
        cudaFuncSetAttribute(attn_fp16, cudaFuncAttributeMaxDynamicSharedMemorySize,
                             AT_SMEM);
        cudaFuncSetAttribute(gemm_qkv, cudaFuncAttributeMaxDynamicSharedMemorySize,
                             GH_SMEM);
        cudaFuncSetAttribute(gemm_o, cudaFuncAttributeMaxDynamicSharedMemorySize,
                             GH_SMEM);
        smem_set = 1;
    }

    prep_kernel<<<NORM_ROWS + WBLOCKS, 256>>>(
        x, ctx, gamma, (const float4*)Wq, (const float4*)Wkv, (const float4*)Wo);

    // merged Q + KV projection: 768 CTAs (128x128 tiles, 2 CTAs/SM)
    gemm_qkv<<<768, 256, GH_SMEM>>>(sq, skv);

    attn_fp16<<<dim3(SEQ_N / 128, BATCH * NHEAD), 256, AT_SMEM>>>(nullkv);

    // O projection: 4096 x 2048 x 1024, 512 CTAs — fp16-accum experiment
    gemm_o<<<dim3(DIMF / 128, (BATCH * SEQ_N) / 128), 256, GH_SMEM>>>(out);
}

// round 13
// speedup vs baseline: 1.0346x; 1.0346x over previous
#include <cuda_runtime.h>
#include <cuda_fp16.h>
#include <math.h>
#include <stdint.h>

#define BATCH 4
#define SEQ_N 1024
#define SEQ_K 1024
#define DIMF  2048
#define NHEAD 16
#define DHEAD 64
#define ROUTES 2
#define HPR   (NHEAD/ROUTES)
#define DHID  (NHEAD*DHEAD)   // 1024

// ---------------- scratch (static device allocations) ----------------
__device__ __half h_xn[(size_t)BATCH*SEQ_N*DIMF];
__device__ __half h_cn[(size_t)BATCH*ROUTES*SEQ_K*DIMF];
__device__ __half h_q [(size_t)BATCH*NHEAD*SEQ_N*DHEAD];
__device__ __half h_k [(size_t)BATCH*NHEAD*SEQ_K*DHEAD];
__device__ __half h_v [(size_t)BATCH*NHEAD*SEQ_K*DHEAD];
__device__ __half h_ao[(size_t)BATCH*SEQ_N*DHID];
__device__ __half h_wq [(size_t)DHID*DIMF];
__device__ __half h_wkv[(size_t)2*DHID*DIMF];
__device__ __half h_wo [(size_t)DIMF*DHID];

// ---------------- helpers ----------------
__device__ __forceinline__ void cp16(void* dst_smem, const void* src) {
    uint32_t d = (uint32_t)__cvta_generic_to_shared(dst_smem);
    asm volatile("cp.async.cg.shared.global [%0], [%1], 16;" :: "r"(d), "l"(src));
}
__device__ __forceinline__ void mma16h(float* c, const uint32_t* a, uint32_t b0, uint32_t b1) {
    asm volatile("mma.sync.aligned.m16n8k16.row.col.f32.f16.f16.f32 "
        "{%0,%1,%2,%3},{%4,%5,%6,%7},{%8,%9},{%0,%1,%2,%3};"
        : "+f"(c[0]), "+f"(c[1]), "+f"(c[2]), "+f"(c[3])
        : "r"(a[0]), "r"(a[1]), "r"(a[2]), "r"(a[3]), "r"(b0), "r"(b1));
}
__device__ __forceinline__ void ldsm4(uint32_t* r, uint32_t addr) {
    asm volatile("ldmatrix.sync.aligned.m8n8.x4.shared.b16 {%0,%1,%2,%3}, [%4];"
        : "=r"(r[0]), "=r"(r[1]), "=r"(r[2]), "=r"(r[3]) : "r"(addr));
}
__device__ __forceinline__ void ldsm4t(uint32_t* r, uint32_t addr) {
    asm volatile("ldmatrix.sync.aligned.m8n8.x4.trans.shared.b16 {%0,%1,%2,%3}, [%4];"
        : "=r"(r[0]), "=r"(r[1]), "=r"(r[2]), "=r"(r[3]) : "r"(addr));
}
__device__ __forceinline__ uint32_t s2u(const void* p) {
    uint32_t a;
    asm("{ .reg .u64 t; cvta.to.shared.u64 t, %1; cvt.u32.u64 %0, t; }"
        : "=r"(a) : "l"(p));
    return a;
}
__device__ __forceinline__ uint32_t packh2(float a, float b) {
    __half2 h = __floats2half2_rn(a, b);
    return *(uint32_t*)&h;
}

// ---------------- prep kernels ----------------
#define WQ_N4  ((DHID * DIMF) / 4)            // 524288
#define WKV_N4 ((2 * DHID * DIMF) / 4)        // 1048576
#define WO_N4  ((DIMF * DHID) / 4)            // 524288
#define NORM_ROWS (BATCH * SEQ_N + BATCH * ROUTES * SEQ_K)   // 12288

// rmsnorm: 2 rows per block (64B in flight per thread, overlapped reductions)
__global__ void __launch_bounds__(256) prep_norm(
    const float* __restrict__ x, const float* __restrict__ ctx,
    const float* __restrict__ gamma)
{
    const long r0 = (long)blockIdx.x * 2;
    const long r1 = r0 + 1;
    const int t = threadIdx.x;

    const float *inA, *inB;
    __half *outA, *outB;
    if (r0 < BATCH * SEQ_N) { inA = x + r0 * (long)DIMF;                    outA = h_xn + r0 * (long)DIMF; }
    else                    { inA = ctx + (r0 - BATCH * SEQ_N) * (long)DIMF; outA = h_cn + (r0 - BATCH * SEQ_N) * (long)DIMF; }
    if (r1 < BATCH * SEQ_N) { inB = x + r1 * (long)DIMF;                    outB = h_xn + r1 * (long)DIMF; }
    else                    { inB = ctx + (r1 - BATCH * SEQ_N) * (long)DIMF; outB = h_cn + (r1 - BATCH * SEQ_N) * (long)DIMF; }

    const float4* xa = (const float4*)inA;
    const float4* xb = (const float4*)inB;
    const float4* g4 = (const float4*)gamma;

    float4 a0 = xa[2 * t], a1 = xa[2 * t + 1];
    float4 b0 = xb[2 * t], b1 = xb[2 * t + 1];

    float sa = a0.x*a0.x + a0.y*a0.y + a0.z*a0.z + a0.w*a0.w
             + a1.x*a1.x + a1.y*a1.y + a1.z*a1.z + a1.w*a1.w;
    float sb = b0.x*b0.x + b0.y*b0.y + b0.z*b0.z + b0.w*b0.w
             + b1.x*b1.x + b1.y*b1.y + b1.z*b1.z + b1.w*b1.w;
    #pragma unroll
    for (int o = 16; o; o >>= 1) {
        sa += __shfl_xor_sync(0xffffffffu, sa, o);
        sb += __shfl_xor_sync(0xffffffffu, sb, o);
    }
    __shared__ float redA[8], redB[8];
    if ((t & 31) == 0) { redA[t >> 5] = sa; redB[t >> 5] = sb; }
    __syncthreads();
    float ta = 0.f, tb = 0.f;
    #pragma unroll
    for (int i = 0; i < 8; i++) { ta += redA[i]; tb += redB[i]; }
    const float scA = sqrtf((float)DIMF) / fmaxf(sqrtf(ta), 1e-12f);
    const float scB = sqrtf((float)DIMF) / fmaxf(sqrtf(tb), 1e-12f);

    float4 g0 = g4[2 * t], g1 = g4[2 * t + 1];
    uint4 pa, pb;
    pa.x = packh2(a0.x*scA*g0.x, a0.y*scA*g0.y);
    pa.y = packh2(a0.z*scA*g0.z, a0.w*scA*g0.w);
    pa.z = packh2(a1.x*scA*g1.x, a1.y*scA*g1.y);
    pa.w = packh2(a1.z*scA*g1.z, a1.w*scA*g1.w);
    pb.x = packh2(b0.x*scB*g0.x, b0.y*scB*g0.y);
    pb.y = packh2(b0.z*scB*g0.z, b0.w*scB*g0.w);
    pb.z = packh2(b1.x*scB*g1.x, b1.y*scB*g1.y);
    pb.w = packh2(b1.z*scB*g1.z, b1.w*scB*g1.w);
    ((uint4*)outA)[t] = pa;
    ((uint4*)outB)[t] = pb;
}

// weight conversion, 4 x float4 per thread (coalesced strided)
__global__ void __launch_bounds__(256) prep_w_qkv(
    const float4* __restrict__ Wq, const float4* __restrict__ Wkv)
{
    const int base = blockIdx.x * 1024 + threadIdx.x;
    #pragma unroll
    for (int u = 0; u < 4; u++) {
        int i = base + u * 256;
        const float4* src;
        __half2* dst;
        int j = i;
        if (j < WQ_N4) { src = Wq; dst = (__half2*)h_wq; }
        else { j -= WQ_N4; src = Wkv; dst = (__half2*)h_wkv; }
        float4 v = src[j];
        dst[2 * j]     = __floats2half2_rn(v.x, v.y);
        dst[2 * j + 1] = __floats2half2_rn(v.z, v.w);
    }
}
__global__ void __launch_bounds__(256) prep_w_o(const float4* __restrict__ Wo)
{
    const int base = blockIdx.x * 1024 + threadIdx.x;
    __half2* dst = (__half2*)h_wo;
    #pragma unroll
    for (int u = 0; u < 4; u++) {
        int j = base + u * 256;
        float4 v = Wo[j];
        dst[2 * j]     = __floats2half2_rn(v.x, v.y);
        dst[2 * j + 1] = __floats2half2_rn(v.z, v.w);
    }
}

// ---------------- fp16 tensor-core GEMM core ----------------
// CTA tile 128x128, BK=64 halves (128B rows), 3-stage cp.async (96KB smem),
// 256 threads (8 warps 2x4), warp tile 64x32, 2 CTAs/SM.
#define GH_STAGE 32768
#define GH_SMEM  (3 * GH_STAGE)

__global__ void __launch_bounds__(256, 2) gemm_qkv(
    const float* __restrict__ sq, const float* __restrict__ skv)
{
    constexpr int K  = DIMF;
    constexpr int NC = K / 64;

    extern __shared__ char smem[];
    const uint32_t smu = s2u(smem);

    const int id = blockIdx.x;
    const bool isQ = (id < 256);
    int bm, bn, bz = 0;
    const __half *A, *Bp;
    if (isQ) {
        bm = id >> 3; bn = id & 7;
        A  = h_xn + (size_t)bm * 128 * K;
        Bp = h_wq + (size_t)bn * 128 * K;
    } else {
        int r = id - 256;
        bz = r >> 6;
        int rr = r & 63;
        bm = rr >> 3; bn = rr & 7;
        A  = h_cn + ((size_t)bz * SEQ_K + (size_t)bm * 128) * K;
        Bp = h_wkv + (size_t)(bz & 1) * DHID * K + (size_t)bn * 128 * K;
    }

    const int tid = threadIdx.x;
    const int lane = tid & 31, warp = tid >> 5;
    const int wm = warp >> 2, wn = warp & 3;
    const int g = lane >> 2, cq = lane & 3;

    const int lr = tid >> 3, lg = tid & 7;
    const int lsw = (lg ^ (lr & 7)) << 4;
    auto load_chunk = [&](int c, int st) {
        char* aB = smem + st * GH_STAGE;
        char* bB = aB + 16384;
        const size_t ko = (size_t)c * 64 + lg * 8;
        #pragma unroll
        for (int t4 = 0; t4 < 4; t4++)
            cp16(aB + (lr + t4 * 32) * 128 + lsw, A + (size_t)(lr + t4 * 32) * K + ko);
        #pragma unroll
        for (int t4 = 0; t4 < 4; t4++)
            cp16(bB + (lr + t4 * 32) * 128 + lsw, Bp + (size_t)(lr + t4 * 32) * K + ko);
    };

    const int lrow = lane & 15, hi = lane >> 4;
    const int sw = lane & 7;
    int moff[4], noff[2];
    #pragma unroll
    for (int mt = 0; mt < 4; mt++) moff[mt] = (wm * 64 + mt * 16 + lrow) * 128;
    #pragma unroll
    for (int p = 0; p < 2; p++)    noff[p]  = (wn * 32 + p * 16 + lrow) * 128 + 16384;

    float c[4][4][4];
    #pragma unroll
    for (int mt = 0; mt < 4; mt++)
        #pragma unroll
        for (int nt = 0; nt < 4; nt++)
            #pragma unroll
            for (int i = 0; i < 4; i++) c[mt][nt][i] = 0.f;

    load_chunk(0, 0);
    asm volatile("cp.async.commit_group;");
    load_chunk(1, 1);
    asm volatile("cp.async.commit_group;");

    #pragma unroll 1
    for (int t = 0; t < NC; t++) {
        asm volatile("cp.async.wait_group 1;");
        __syncthreads();

        if (t + 2 < NC) load_chunk(t + 2, (t + 2) % 3);
        asm volatile("cp.async.commit_group;");

        const uint32_t sb = smu + (t % 3) * GH_STAGE;

        #pragma unroll
        for (int ks = 0; ks < 4; ks++) {
            const int koff = ((2 * ks + hi) ^ sw) << 4;
            uint32_t af[4][4], bf[2][4];
            #pragma unroll
            for (int mt = 0; mt < 4; mt++) ldsm4(af[mt], sb + moff[mt] + koff);
            #pragma unroll
            for (int p = 0; p < 2; p++)    ldsm4(bf[p], sb + noff[p] + koff);
            #pragma unroll
            for (int mt = 0; mt < 4; mt++)
                #pragma unroll
                for (int nt = 0; nt < 4; nt++)
                    mma16h(c[mt][nt], af[mt], bf[nt >> 1][nt & 1], bf[nt >> 1][(nt & 1) + 2]);
        }
    }

    #pragma unroll
    for (int mt = 0; mt < 4; mt++) {
        #pragma unroll
        for (int i = 0; i < 2; i++) {
            const int m = bm * 128 + wm * 64 + mt * 16 + g + i * 8;
            const float srow = isQ ? sq[m] * 0.125f : skv[(size_t)bz * SEQ_K + m];
            #pragma unroll
            for (int nt = 0; nt < 4; nt++) {
                const int o = bn * 128 + wn * 32 + (nt >> 1) * 16 + (nt & 1) * 8 + 2 * cq;
                float v0 = c[mt][nt][i * 2 + 0];
                float v1 = c[mt][nt][i * 2 + 1];
                __half2 hv = __floats2half2_rn(v0 * srow, v1 * srow);
                if (isQ) {
                    int b = m >> 10, nn = m & 1023;
                    int h = o >> 6,  d  = o & 63;
                    *(__half2*)&h_q[(((size_t)(b * NHEAD + h)) * SEQ_N + nn) * DHEAD + d] = hv;
                } else {
                    int hp = o >> 7, dd = o & 127;
                    int b = bz >> 1, rt = bz & 1;
                    size_t base = (((size_t)(b * NHEAD + rt * HPR + hp)) * SEQ_K + m) * DHEAD;
                    if (dd < DHEAD) *(__half2*)&h_k[base + dd]         = hv;
                    else            *(__half2*)&h_v[base + dd - DHEAD] = hv;
                }
            }
        }
    }
}

// ---- O projection (K = 1024), fp32 accum, 2 CTAs/SM (R11 best) ----
__global__ void __launch_bounds__(256, 2) gemm_o(float* __restrict__ out)
{
    constexpr int K  = DHID;
    constexpr int NC = K / 64;

    extern __shared__ char smem[];
    const uint32_t smu = s2u(smem);

    const int bm = blockIdx.y, bn = blockIdx.x;
    const int tid = threadIdx.x;
    const int lane = tid & 31, warp = tid >> 5;
    const int wm = warp >> 2, wn = warp & 3;
    const int g = lane >> 2, cq = lane & 3;

    const __half* A  = h_ao + (size_t)bm * 128 * K;
    const __half* Bp = h_wo + (size_t)bn * 128 * K;

    const int lr = tid >> 3, lg = tid & 7;
    const int lsw = (lg ^ (lr & 7)) << 4;
    auto load_chunk = [&](int c, int st) {
        char* aB = smem + st * GH_STAGE;
        char* bB = aB + 16384;
        const size_t ko = (size_t)c * 64 + lg * 8;
        #pragma unroll
        for (int t4 = 0; t4 < 4; t4++)
            cp16(aB + (lr + t4 * 32) * 128 + lsw, A + (size_t)(lr + t4 * 32) * K + ko);
        #pragma unroll
        for (int t4 = 0; t4 < 4; t4++)
            cp16(bB + (lr + t4 * 32) * 128 + lsw, Bp + (size_t)(lr + t4 * 32) * K + ko);
    };

    const int lrow = lane & 15, hi = lane >> 4;
    const int sw = lane & 7;
    int moff[4], noff[2];
    #pragma unroll
    for (int mt = 0; mt < 4; mt++) moff[mt] = (wm * 64 + mt * 16 + lrow) * 128;
    #pragma unroll
    for (int p = 0; p < 2; p++)    noff[p]  = (wn * 32 + p * 16 + lrow) * 128 + 16384;

    float c[4][4][4];
    #pragma unroll
    for (int mt = 0; mt < 4; mt++)
        #pragma unroll
        for (int nt = 0; nt < 4; nt++)
            #pragma unroll
            for (int i = 0; i < 4; i++) c[mt][nt][i] = 0.f;

    load_chunk(0, 0);
    asm volatile("cp.async.commit_group;");
    load_chunk(1, 1);
    asm volatile("cp.async.commit_group;");

    #pragma unroll 1
    for (int t = 0; t < NC; t++) {
        asm volatile("cp.async.wait_group 1;");
        __syncthreads();

        if (t + 2 < NC) load_chunk(t + 2, (t + 2) % 3);
        asm volatile("cp.async.commit_group;");

        const uint32_t sb = smu + (t % 3) * GH_STAGE;

        #pragma unroll
        for (int ks = 0; ks < 4; ks++) {
            const int koff = ((2 * ks + hi) ^ sw) << 4;
            uint32_t af[4][4], bf[2][4];
            #pragma unroll
            for (int mt = 0; mt < 4; mt++) ldsm4(af[mt], sb + moff[mt] + koff);
            #pragma unroll
            for (int p = 0; p < 2; p++)    ldsm4(bf[p], sb + noff[p] + koff);
            #pragma unroll
            for (int mt = 0; mt < 4; mt++)
                #pragma unroll
                for (int nt = 0; nt < 4; nt++)
                    mma16h(c[mt][nt], af[mt], bf[nt >> 1][nt & 1], bf[nt >> 1][(nt & 1) + 2]);
        }
    }

    #pragma unroll
    for (int mt = 0; mt < 4; mt++) {
        #pragma unroll
        for (int i = 0; i < 2; i++) {
            const int m = bm * 128 + wm * 64 + mt * 16 + g + i * 8;
            #pragma unroll
            for (int nt = 0; nt < 4; nt++) {
                const int o = bn * 128 + wn * 32 + (nt >> 1) * 16 + (nt & 1) * 8 + 2 * cq;
                *(float2*)&out[(size_t)m * DIMF + o] =
                    make_float2(c[mt][nt][i * 2 + 0], c[mt][nt][i * 2 + 1]);
            }
        }
    }
}

// ---------------- fp16 flash attention, P kept in registers ----------------
#define AT_SMEM 49664

__global__ void __launch_bounds__(256, 2) attn_fp16(const float* __restrict__ nullkv)
{
    extern __shared__ __half sh[];
    __half* qs = sh;
    __half* ks = sh + 8192;
    __half* vs = sh + 16384;
    float* nk = (float*)(sh + 24576);
    float* nv = nk + 64;
    const uint32_t smu = s2u(sh);

    const int bh = blockIdx.y, h = bh & (NHEAD - 1);
    const int qbase = blockIdx.x * 128;
    const int tid = threadIdx.x, lane = tid & 31, w = tid >> 5;
    const int g = lane >> 2, cq = lane & 3;
    const int lrow = lane & 15, hi = lane >> 4;
    const int sw = lane & 7;

    const __half* qg = h_q + ((size_t)bh * SEQ_N + qbase) * DHEAD;
    const __half* kgp = h_k + (size_t)bh * SEQ_K * DHEAD;
    const __half* vgp = h_v + (size_t)bh * SEQ_K * DHEAD;

    #pragma unroll
    for (int i = 0; i < 4; i++) {
        int idx = tid + i * 256;
        int r = idx >> 3, gg = idx & 7;
        cp16(qs + r * 64 + ((gg ^ (r & 7)) << 3), qg + (size_t)r * DHEAD + gg * 8);
    }
    if (tid < 64)       nk[tid]      = nullkv[h * DHEAD + tid];
    else if (tid < 128) nv[tid - 64] = nullkv[NHEAD * DHEAD + h * DHEAD + (tid - 64)];

    auto load_kv = [&](int tile, int buf) {
        const __half* kt = kgp + (size_t)tile * 64 * DHEAD;
        const __half* vt = vgp + (size_t)tile * 64 * DHEAD;
        __half* kd = ks + buf * 4096;
        __half* vd = vs + buf * 4096;
        #pragma unroll
        for (int i = 0; i < 2; i++) {
            int idx = tid + i * 256;
            int r = idx >> 3, gg = idx & 7;
            int off = r * 64 + ((gg ^ (r & 7)) << 3);
            cp16(kd + off, kt + (size_t)r * DHEAD + gg * 8);
            cp16(vd + off, vt + (size_t)r * DHEAD + gg * 8);
        }
    };
    load_kv(0, 0);
    asm volatile("cp.async.commit_group;");

    asm volatile("cp.async.wait_group 0;");
    __syncthreads();

    float m0, m1, l0 = 1.f, l1 = 1.f;
    {
        int row = w * 16 + lrow;
        int halfo = hi * 32;
        float s = 0.f;
        #pragma unroll
        for (int d = 0; d < 32; d++) {
            int cidx = halfo + d;
            int gg = cidx >> 3;
            float qv = __half2float(qs[row * 64 + ((gg ^ (row & 7)) << 3) + (cidx & 7)]);
            s += qv * nk[cidx];
        }
        s += __shfl_xor_sync(0xffffffffu, s, 16);
        m0 = __shfl_sync(0xffffffffu, s, g);
        m1 = __shfl_sync(0xffffffffu, s, g + 8);
    }
    float o[8][4];
    #pragma unroll
    for (int nt = 0; nt < 8; nt++) {
        float va = nv[nt * 8 + 2 * cq], vb = nv[nt * 8 + 2 * cq + 1];
        o[nt][0] = va; o[nt][1] = vb; o[nt][2] = va; o[nt][3] = vb;
    }

    const uint32_t aqbase = smu + (w * 16 + lrow) * 128;

    #pragma unroll 1
    for (int t = 0; t < 16; t++) {
        if (t > 0) {
            asm volatile("cp.async.wait_group 0;");
            __syncthreads();
        }
        if (t + 1 < 16) load_kv(t + 1, (t + 1) & 1);
        asm volatile("cp.async.commit_group;");

        const uint32_t kbB = smu + 16384 + (t & 1) * 8192 + lrow * 128;
        const uint32_t vbB = smu + 32768 + (t & 1) * 8192 + lrow * 128;

        float s[8][4];
        #pragma unroll
        for (int nt = 0; nt < 8; nt++)
            s[nt][0] = s[nt][1] = s[nt][2] = s[nt][3] = 0.f;

        #pragma unroll
        for (int kst = 0; kst < 4; kst++) {
            const int koff = ((2 * kst + hi) ^ sw) << 4;
            uint32_t af[4], bf[4][4];
            ldsm4(af, aqbase + koff);
            #pragma unroll
            for (int p = 0; p < 4; p++) ldsm4(bf[p], kbB + p * 2048 + koff);
            #pragma unroll
            for (int nt = 0; nt < 8; nt++)
                mma16h(s[nt], af, bf[nt >> 1][nt & 1], bf[nt >> 1][(nt & 1) + 2]);
        }

        float mx0 = -1e30f, mx1 = -1e30f;
        #pragma unroll
        for (int nt = 0; nt < 8; nt++) {
            mx0 = fmaxf(mx0, fmaxf(s[nt][0], s[nt][1]));
            mx1 = fmaxf(mx1, fmaxf(s[nt][2], s[nt][3]));
        }
        mx0 = fmaxf(mx0, __shfl_xor_sync(0xffffffffu, mx0, 1));
        mx0 = fmaxf(mx0, __shfl_xor_sync(0xffffffffu, mx0, 2));
        mx1 = fmaxf(mx1, __shfl_xor_sync(0xffffffffu, mx1, 1));
        mx1 = fmaxf(mx1, __shfl_xor_sync(0xffffffffu, mx1, 2));
        float mn0 = fmaxf(m0, mx0), mn1 = fmaxf(m1, mx1);
        float c0 = __expf(m0 - mn0), c1 = __expf(m1 - mn1);
        float p0 = 0.f, p1 = 0.f;
        #pragma unroll
        for (int nt = 0; nt < 8; nt++) {
            s[nt][0] = __expf(s[nt][0] - mn0);
            s[nt][1] = __expf(s[nt][1] - mn0);
            s[nt][2] = __expf(s[nt][2] - mn1);
            s[nt][3] = __expf(s[nt][3] - mn1);
            p0 += s[nt][0] + s[nt][1];
            p1 += s[nt][2] + s[nt][3];
        }
        p0 += __shfl_xor_sync(0xffffffffu, p0, 1);
        p0 += __shfl_xor_sync(0xffffffffu, p0, 2);
        p1 += __shfl_xor_sync(0xffffffffu, p1, 1);
        p1 += __shfl_xor_sync(0xffffffffu, p1, 2);
        l0 = l0 * c0 + p0; l1 = l1 * c1 + p1;
        m0 = mn0; m1 = mn1;
        #pragma unroll
        for (int nt = 0; nt < 8; nt++) {
            o[nt][0] *= c0; o[nt][1] *= c0;
            o[nt][2] *= c1; o[nt][3] *= c1;
        }

        #pragma unroll
        for (int kc = 0; kc < 4; kc++) {
            uint32_t ap[4];
            ap[0] = packh2(s[2 * kc][0],     s[2 * kc][1]);
            ap[1] = packh2(s[2 * kc][2],     s[2 * kc][3]);
            ap[2] = packh2(s[2 * kc + 1][0], s[2 * kc + 1][1]);
            ap[3] = packh2(s[2 * kc + 1][2], s[2 * kc + 1][3]);
            #pragma unroll
            for (int nt2 = 0; nt2 < 4; nt2++) {
                const int voff = ((nt2 * 2 + hi) ^ sw) << 4;
                uint32_t tv[4];
                ldsm4t(tv, vbB + kc * 2048 + voff);
                mma16h(o[2 * nt2],     ap, tv[0], tv[1]);
                mma16h(o[2 * nt2 + 1], ap, tv[2], tv[3]);
            }
        }
    }

    const int b = bh >> 4;
    const float i0 = 1.f / l0, i1 = 1.f / l1;
    const int n0 = qbase + w * 16 + g;
    const size_t base0 = ((size_t)(b * SEQ_N + n0)) * DHID + h * DHEAD;
    const size_t base1 = ((size_t)(b * SEQ_N + n0 + 8)) * DHID + h * DHEAD;
    #pragma unroll
    for (int nt = 0; nt < 8; nt++) {
        int col = nt * 8 + 2 * cq;
        *(__half2*)&h_ao[base0 + col] = __floats2half2_rn(o[nt][0] * i0, o[nt][1] * i0);
        *(__half2*)&h_ao[base1 + col] = __floats2half2_rn(o[nt][2] * i1, o[nt][3] * i1);
    }
}

// ---------------- launch ----------------
extern "C" void kernel_launch(void* const* d_in, const int* in_sizes, int n_in,
                              void* d_out, int out_size)
{
    const float* x      = (const float*)d_in[0];
    const float* ctx    = (const float*)d_in[1];
    const float* skv    = (const float*)d_in[2];
    const float* sq     = (const float*)d_in[3];
    const float* gamma  = (const float*)d_in[4];
    const float* nullkv = (const float*)d_in[5];
    const float* Wq     = (const float*)d_in[6];
    const float* Wkv    = (const float*)d_in[7];
    const float* Wo     = (const float*)d_in[8];
    float* out = (float*)d_out;

    static cudaStream_t s2;
    static cudaEvent_t eFork, eWo;
    static int inited = 0;
    if (!inited) {
        cudaFuncSetAttribute(attn_fp16, cudaFuncAttributeMaxDynamicSharedMemorySize,
                             AT_SMEM);
        cudaFuncSetAttribute(gemm_qkv, cudaFuncAttributeMaxDynamicSharedMemorySize,
                             GH_SMEM);
        cudaFuncSetAttribute(gemm_o, cudaFuncAttributeMaxDynamicSharedMemorySize,
                             GH_SMEM);
        cudaStreamCreateWithFlags(&s2, cudaStreamNonBlocking);
        cudaEventCreateWithFlags(&eFork, cudaEventDisableTiming);
        cudaEventCreateWithFlags(&eWo, cudaEventDisableTiming);
        inited = 1;
    }

    // fork: Wo weight conversion overlaps the tensor-bound gemm_qkv
    cudaEventRecord(eFork, 0);
    cudaStreamWaitEvent(s2, eFork, 0);
    prep_w_o<<<WO_N4 / 1024, 256, 0, s2>>>((const float4*)Wo);
    cudaEventRecord(eWo, s2);

    // main chain
    prep_norm<<<NORM_ROWS / 2, 256>>>(x, ctx, gamma);
    prep_w_qkv<<<(WQ_N4 + WKV_N4) / 1024, 256>>>((const float4*)Wq, (const float4*)Wkv);

    gemm_qkv<<<768, 256, GH_SMEM>>>(sq, skv);

    attn_fp16<<<dim3(SEQ_N / 128, BATCH * NHEAD), 256, AT_SMEM>>>(nullkv);

    // join: gemm_o needs h_wo
    cudaStreamWaitEvent(0, eWo, 0);
    gemm_o<<<dim3(DIMF / 128, (BATCH * SEQ_N) / 128), 256, GH_SMEM>>>(out);
}